// round 11
// baseline (speedup 1.0000x reference)
#include <cuda_runtime.h>
#include <cstdint>

// Filtering_72773925863700
// out[b,m,n,i] = (F x)_along_m + (F x)_along_n,  F = C C^T (256x32 low-rank,
// C = ortho-normalized cos/sin basis for rfft modes [0,16), exact identity).
// B=8, M=N=256, I=32, fp32.
//
// Round 11 (= R10 with the cvt fix): tf32 cvt destination must be .b32
// ("=r"), not .f32 — that was the only compile failure. k3 -> tf32 tensor
// cores (mma.sync.m16n8k8) as two pure GEMMs:
//   k3a: out  = Cm[256x32] x D1[32x8192]   (cols = (n,i), i innermost)
//   k3b: out += Cn[256x32] x D2[32x8192]   (cols = (m,i), i innermost)
// D2 stored [b][k][(m,i)]. D1/D2 written tf32-rounded; A uses d_Ct. No smem
// or syncs in k3a/k3b. k1/k2 are the proven R7 bulk-async versions.

#define BATCH 8
#define MDIM 256
#define NDIM 256
#define IDIM 32
#define KM 32
#define NI (NDIM * IDIM)   // 8192

__device__ float d_C[MDIM * KM];                   // C[n][k]  (fp32)
__device__ float d_Ct[MDIM * KM];                  // C[n][k]  (tf32-rounded)
__device__ float d_D1[BATCH * KM * NI];            // [b][k][(n,i)]  tf32 vals
__device__ float d_D2[BATCH * KM * NI];            // [b][k][(m,i)]  tf32 vals

union F4U { float4 f4; uint64_t u[2]; float f[4]; };

__device__ __forceinline__ uint64_t pack2(float c) {
    uint64_t r;
    asm("mov.b64 %0, {%1, %1};" : "=l"(r) : "f"(c));
    return r;
}
__device__ __forceinline__ void fma2(uint64_t& acc, uint64_t a, uint64_t b) {
    asm("fma.rn.f32x2 %0, %1, %2, %0;" : "+l"(acc) : "l"(a), "l"(b));
}
__device__ __forceinline__ float to_tf32(float x) {
    uint32_t r;
    asm("cvt.rna.tf32.f32 %0, %1;" : "=r"(r) : "f"(x));
    return __uint_as_float(r);
}
__device__ __forceinline__ uint32_t sm_addr(const void* p) {
    uint32_t a;
    asm("{ .reg .u64 t; cvta.to.shared.u64 t, %1; cvt.u32.u64 %0, t; }"
        : "=r"(a) : "l"(p));
    return a;
}
__device__ __forceinline__ void mbar_init(uint32_t mbar, uint32_t count) {
    asm volatile("mbarrier.init.shared.b64 [%0], %1;" :: "r"(mbar), "r"(count) : "memory");
}
__device__ __forceinline__ void mbar_expect(uint32_t mbar, uint32_t bytes) {
    asm volatile("mbarrier.arrive.expect_tx.shared.b64 _, [%0], %1;"
                 :: "r"(mbar), "r"(bytes) : "memory");
}
__device__ __forceinline__ void bulk_g2s(uint32_t dst, const void* src,
                                         uint32_t bytes, uint32_t mbar) {
    asm volatile(
        "cp.async.bulk.shared::cta.global.mbarrier::complete_tx::bytes [%0], [%1], %2, [%3];"
        :: "r"(dst), "l"(src), "r"(bytes), "r"(mbar) : "memory");
}
__device__ __forceinline__ void mbar_wait(uint32_t mbar, uint32_t parity) {
    asm volatile(
        "{\n\t"
        ".reg .pred P1;\n\t"
        "WAIT_LOOP_%=:\n\t"
        "mbarrier.try_wait.parity.acquire.cta.shared::cta.b64 P1, [%0], %1;\n\t"
        "@P1 bra.uni WAIT_DONE_%=;\n\t"
        "bra.uni WAIT_LOOP_%=;\n\t"
        "WAIT_DONE_%=:\n\t"
        "}"
        :: "r"(mbar), "r"(parity) : "memory");
}

// mma.sync m16n8k8 tf32: D += A x B, frags per PTX ISA thread mapping.
__device__ __forceinline__ void mma_tf32(float* d, const uint32_t* a,
                                         uint32_t b0, uint32_t b1) {
    asm volatile(
        "mma.sync.aligned.m16n8k8.row.col.f32.tf32.tf32.f32 "
        "{%0,%1,%2,%3}, {%4,%5,%6,%7}, {%8,%9}, {%0,%1,%2,%3};"
        : "+f"(d[0]), "+f"(d[1]), "+f"(d[2]), "+f"(d[3])
        : "r"(a[0]), "r"(a[1]), "r"(a[2]), "r"(a[3]), "r"(b0), "r"(b1));
}

// ---------------------------------------------------------------------------
// Init C[n][j] (fp32) and tf32-rounded copy.
// ---------------------------------------------------------------------------
__global__ void init_C_kernel() {
    int idx = blockIdx.x * 256 + threadIdx.x;   // 8192 total
    int n = idx >> 5;
    int j = idx & 31;
    const double PI = 3.14159265358979323846;
    const double AMP = 1.4142135623730951 / 16.0;
    double v;
    if (j == 0) {
        v = 1.0 / 16.0;
    } else if (j <= 15) {
        int ph = (j * n) & 255;
        v = AMP * cos(2.0 * PI * (double)ph / 256.0);
    } else if (j <= 30) {
        int k = j - 15;
        int ph = (k * n) & 255;
        v = AMP * sin(2.0 * PI * (double)ph / 256.0);
    } else {
        v = 0.0;
    }
    float f = (float)v;
    d_C[idx]  = f;
    d_Ct[idx] = to_tf32(f);
}

// ---------------------------------------------------------------------------
// K1: D1[b,k,(n,i)] = sum_m C[m,k] * x[b,m,n,i]   (R7 bulk-async version)
// Block (jt, b): tile [32k x 256j], 128 thr. ko=t>>5 (8 k), jq=t&31.
// ---------------------------------------------------------------------------
__global__ void __launch_bounds__(128) k1_down_m(const float* __restrict__ x) {
    __shared__ __align__(128) float xs[2][8 * 256];
    __shared__ __align__(128) float cs[2][8 * 32];
    __shared__ __align__(8) uint64_t mbar[2];

    int t  = threadIdx.x;
    int b  = blockIdx.y;
    int j0 = blockIdx.x * 256;
    int jq = t & 31;
    int ko = t >> 5;

    const float* xb = x + (size_t)b * (MDIM * NI);
    uint32_t mb0 = sm_addr(&mbar[0]);
    uint32_t mb1 = sm_addr(&mbar[1]);

    if (t == 0) { mbar_init(mb0, 1); mbar_init(mb1, 1); }
    __syncthreads();

    const uint32_t CHUNK_BYTES = 8 * 256 * 4 + 8 * 32 * 4;

    auto issue = [&](int mc, int s) {
        uint32_t mb = s ? mb1 : mb0;
        mbar_expect(mb, CHUNK_BYTES);
#pragma unroll
        for (int mm = 0; mm < 8; mm++)
            bulk_g2s(sm_addr(&xs[s][mm * 256]),
                     &xb[(size_t)(mc * 8 + mm) * NI + j0], 1024, mb);
        bulk_g2s(sm_addr(&cs[s][0]), &d_C[mc * 8 * 32], 1024, mb);
    };

    uint64_t acc[8][4];
#pragma unroll
    for (int a = 0; a < 8; a++)
#pragma unroll
        for (int q = 0; q < 4; q++) acc[a][q] = 0ull;

    if (t == 0) issue(0, 0);
    for (int mc = 0; mc < 32; mc++) {
        int s = mc & 1;
        if (mc + 1 < 32) {
            __syncthreads();
            if (t == 0) issue(mc + 1, s ^ 1);
        }
        mbar_wait(s ? mb1 : mb0, (mc >> 1) & 1);

        const float* xsb = xs[s];
        const float* csb = cs[s];
#pragma unroll
        for (int mm = 0; mm < 8; mm++) {
            F4U x0; x0.f4 = *(const float4*)&xsb[mm * 256 + jq * 4];
            F4U x1; x1.f4 = *(const float4*)&xsb[mm * 256 + 128 + jq * 4];
            F4U c0; c0.f4 = *(const float4*)&csb[mm * 32 + ko * 8];
            F4U c1; c1.f4 = *(const float4*)&csb[mm * 32 + ko * 8 + 4];
            float cv[8] = {c0.f[0], c0.f[1], c0.f[2], c0.f[3],
                           c1.f[0], c1.f[1], c1.f[2], c1.f[3]};
#pragma unroll
            for (int a = 0; a < 8; a++) {
                uint64_t cp = pack2(cv[a]);
                fma2(acc[a][0], cp, x0.u[0]);
                fma2(acc[a][1], cp, x0.u[1]);
                fma2(acc[a][2], cp, x1.u[0]);
                fma2(acc[a][3], cp, x1.u[1]);
            }
        }
    }

#pragma unroll
    for (int a = 0; a < 8; a++) {
        int k = ko * 8 + a;
        F4U v0; v0.u[0] = acc[a][0]; v0.u[1] = acc[a][1];
        F4U v1; v1.u[0] = acc[a][2]; v1.u[1] = acc[a][3];
#pragma unroll
        for (int q = 0; q < 4; q++) { v0.f[q] = to_tf32(v0.f[q]); v1.f[q] = to_tf32(v1.f[q]); }
        *(float4*)&d_D1[((size_t)b * 32 + k) * NI + j0 + jq * 4]       = v0.f4;
        *(float4*)&d_D1[((size_t)b * 32 + k) * NI + j0 + 128 + jq * 4] = v1.f4;
    }
}

// ---------------------------------------------------------------------------
// K2: D2[b,k,(m,i)] = sum_n C[n,k] * x[b,m,n,i]   (R7 version, new layout)
// Block (mt of 8 m, b), 256 thr. kq=t&3 (8 k), iq=(t>>2)&7 (4 i), ml=t>>5.
// ---------------------------------------------------------------------------
__global__ void __launch_bounds__(256) k2_down_n(const float* __restrict__ x) {
    __shared__ __align__(128) float zs[2][8 * 16 * 32];
    __shared__ __align__(128) float ch[2][16 * 32];
    __shared__ __align__(8) uint64_t mbar[2];

    int t  = threadIdx.x;
    int b  = blockIdx.y;
    int m0 = blockIdx.x * 8;
    int kq = t & 3;
    int iq = (t >> 2) & 7;
    int ml = t >> 5;

    const float* xb = x + (size_t)b * (MDIM * NI) + (size_t)m0 * NI;
    uint32_t mb0 = sm_addr(&mbar[0]);
    uint32_t mb1 = sm_addr(&mbar[1]);

    if (t == 0) { mbar_init(mb0, 1); mbar_init(mb1, 1); }
    __syncthreads();

    const uint32_t CHUNK_BYTES = 8 * 16 * 32 * 4 + 16 * 32 * 4;

    auto issue = [&](int nc, int s) {
        uint32_t mb = s ? mb1 : mb0;
        mbar_expect(mb, CHUNK_BYTES);
#pragma unroll
        for (int m2 = 0; m2 < 8; m2++)
            bulk_g2s(sm_addr(&zs[s][m2 * 16 * 32]),
                     &xb[(size_t)m2 * NI + nc * 16 * 32], 2048, mb);
        bulk_g2s(sm_addr(&ch[s][0]), &d_C[nc * 16 * 32], 2048, mb);
    };

    uint64_t acc[8][2];
#pragma unroll
    for (int kk = 0; kk < 8; kk++) { acc[kk][0] = 0ull; acc[kk][1] = 0ull; }

    if (t == 0) issue(0, 0);
    for (int nc = 0; nc < 16; nc++) {
        int s = nc & 1;
        if (nc + 1 < 16) {
            __syncthreads();
            if (t == 0) issue(nc + 1, s ^ 1);
        }
        mbar_wait(s ? mb1 : mb0, (nc >> 1) & 1);

        const float* zb = zs[s];
        const float* cb = ch[s];
#pragma unroll
        for (int nn = 0; nn < 16; nn++) {
            F4U z; z.f4 = *(const float4*)&zb[(ml * 16 + nn) * 32 + iq * 4];
            F4U c0; c0.f4 = *(const float4*)&cb[nn * 32 + kq * 8];
            F4U c1; c1.f4 = *(const float4*)&cb[nn * 32 + kq * 8 + 4];
            float cv[8] = {c0.f[0], c0.f[1], c0.f[2], c0.f[3],
                           c1.f[0], c1.f[1], c1.f[2], c1.f[3]};
#pragma unroll
            for (int kk = 0; kk < 8; kk++) {
                uint64_t cp = pack2(cv[kk]);
                fma2(acc[kk][0], cp, z.u[0]);
                fma2(acc[kk][1], cp, z.u[1]);
            }
        }
    }

#pragma unroll
    for (int kk = 0; kk < 8; kk++) {
        int k = kq * 8 + kk;
        F4U v; v.u[0] = acc[kk][0]; v.u[1] = acc[kk][1];
#pragma unroll
        for (int q = 0; q < 4; q++) v.f[q] = to_tf32(v.f[q]);
        // layout: [b][k][(m,i)]
        *(float4*)&d_D2[((size_t)b * 32 + k) * NI + (m0 + ml) * 32 + iq * 4] = v.f4;
    }
}

// ---------------------------------------------------------------------------
// K3a: out[b][m][col] = sum_k Ct[m,k] * D1[b][k][col],  col = (n,i), i fast.
// Grid (ct=8, mt=8, b=8), 512 thr. Warp owns 64 cols (8 col-frags), 32 m rows
// (2 row-frags), K=32 (4 k-frags). No smem, B via __ldg from L2.
// ---------------------------------------------------------------------------
__global__ void __launch_bounds__(512) k3a_up(float* __restrict__ out) {
    int t = threadIdx.x, lane = t & 31, w = t >> 5;
    int ct = blockIdx.x, mt = blockIdx.y, b = blockIdx.z;
    int gr = lane >> 2, tg = lane & 3;
    int colbase = ct * 1024 + w * 64;
    int m0 = mt * 32;

    uint32_t a[2][4][4];
#pragma unroll
    for (int rf = 0; rf < 2; rf++)
#pragma unroll
        for (int kf = 0; kf < 4; kf++) {
            int r = m0 + rf * 16 + gr;
            int c = kf * 8 + tg;
            a[rf][kf][0] = __float_as_uint(d_Ct[r * 32 + c]);
            a[rf][kf][1] = __float_as_uint(d_Ct[(r + 8) * 32 + c]);
            a[rf][kf][2] = __float_as_uint(d_Ct[r * 32 + c + 4]);
            a[rf][kf][3] = __float_as_uint(d_Ct[(r + 8) * 32 + c + 4]);
        }

    const float* B = d_D1 + (size_t)b * 32 * NI;

    float acc[8][2][4];
#pragma unroll
    for (int cf = 0; cf < 8; cf++)
#pragma unroll
        for (int rf = 0; rf < 2; rf++)
#pragma unroll
            for (int q = 0; q < 4; q++) acc[cf][rf][q] = 0.f;

#pragma unroll
    for (int cf = 0; cf < 8; cf++) {
        int col = colbase + cf * 8 + gr;
#pragma unroll
        for (int kf = 0; kf < 4; kf++) {
            int kr = kf * 8 + tg;
            uint32_t b0 = __float_as_uint(__ldg(&B[(size_t)kr * NI + col]));
            uint32_t b1 = __float_as_uint(__ldg(&B[(size_t)(kr + 4) * NI + col]));
            mma_tf32(acc[cf][0], a[0][kf], b0, b1);
            mma_tf32(acc[cf][1], a[1][kf], b0, b1);
        }
    }

#pragma unroll
    for (int cf = 0; cf < 8; cf++)
#pragma unroll
        for (int rf = 0; rf < 2; rf++) {
            int r = m0 + rf * 16 + gr;
            size_t base = ((size_t)b * 256 + r) * NI + colbase + cf * 8 + 2 * tg;
            float2 v0 = make_float2(acc[cf][rf][0], acc[cf][rf][1]);
            float2 v1 = make_float2(acc[cf][rf][2], acc[cf][rf][3]);
            *(float2*)&out[base]            = v0;
            *(float2*)&out[base + 8 * NI]   = v1;   // row r+8
        }
}

// ---------------------------------------------------------------------------
// K3b: out[b][m][n][i] += sum_k Ct[n,k] * D2[b][k][col],  col = (m,i), i fast.
// Grid (ct=8, nt=8, b=8), 512 thr. Same frag scheme; epilogue does float2
// read-add-write into out (L2-hot from k3a).
// ---------------------------------------------------------------------------
__global__ void __launch_bounds__(512) k3b_up(float* __restrict__ out) {
    int t = threadIdx.x, lane = t & 31, w = t >> 5;
    int ct = blockIdx.x, nt = blockIdx.y, b = blockIdx.z;
    int gr = lane >> 2, tg = lane & 3;
    int colbase = ct * 1024 + w * 64;
    int n0 = nt * 32;

    uint32_t a[2][4][4];
#pragma unroll
    for (int rf = 0; rf < 2; rf++)
#pragma unroll
        for (int kf = 0; kf < 4; kf++) {
            int r = n0 + rf * 16 + gr;
            int c = kf * 8 + tg;
            a[rf][kf][0] = __float_as_uint(d_Ct[r * 32 + c]);
            a[rf][kf][1] = __float_as_uint(d_Ct[(r + 8) * 32 + c]);
            a[rf][kf][2] = __float_as_uint(d_Ct[r * 32 + c + 4]);
            a[rf][kf][3] = __float_as_uint(d_Ct[(r + 8) * 32 + c + 4]);
        }

    const float* B = d_D2 + (size_t)b * 32 * NI;

    float acc[8][2][4];
#pragma unroll
    for (int cf = 0; cf < 8; cf++)
#pragma unroll
        for (int rf = 0; rf < 2; rf++)
#pragma unroll
            for (int q = 0; q < 4; q++) acc[cf][rf][q] = 0.f;

#pragma unroll
    for (int cf = 0; cf < 8; cf++) {
        int col = colbase + cf * 8 + gr;
#pragma unroll
        for (int kf = 0; kf < 4; kf++) {
            int kr = kf * 8 + tg;
            uint32_t b0 = __float_as_uint(__ldg(&B[(size_t)kr * NI + col]));
            uint32_t b1 = __float_as_uint(__ldg(&B[(size_t)(kr + 4) * NI + col]));
            mma_tf32(acc[cf][0], a[0][kf], b0, b1);
            mma_tf32(acc[cf][1], a[1][kf], b0, b1);
        }
    }

#pragma unroll
    for (int cf = 0; cf < 8; cf++) {
        int cb = colbase + cf * 8;        // 8-aligned, inside one m (32-block)
        int m  = cb >> 5;
        int ib = (cb & 31) + 2 * tg;
#pragma unroll
        for (int rf = 0; rf < 2; rf++) {
            int n = n0 + rf * 16 + gr;
            size_t ad = (size_t)b * (256 * NI) + (size_t)m * NI + n * 32 + ib;
            float2 o0 = *(float2*)&out[ad];
            o0.x += acc[cf][rf][0];
            o0.y += acc[cf][rf][1];
            *(float2*)&out[ad] = o0;
            size_t ad2 = ad + 8 * 32;     // row n+8
            float2 o1 = *(float2*)&out[ad2];
            o1.x += acc[cf][rf][2];
            o1.y += acc[cf][rf][3];
            *(float2*)&out[ad2] = o1;
        }
    }
}

// ---------------------------------------------------------------------------
extern "C" void kernel_launch(void* const* d_in, const int* in_sizes, int n_in,
                              void* d_out, int out_size) {
    const float* x = (const float*)d_in[0];
    float* out = (float*)d_out;

    init_C_kernel<<<32, 256>>>();
    k1_down_m<<<dim3(32, 8), 128>>>(x);
    k2_down_n<<<dim3(32, 8), 256>>>(x);
    k3a_up<<<dim3(8, 8, 8), 512>>>(out);
    k3b_up<<<dim3(8, 8, 8), 512>>>(out);
}

// round 13
// speedup vs baseline: 1.0907x; 1.0907x over previous
#include <cuda_runtime.h>
#include <cstdint>

// Filtering_72773925863700
// out[b,m,n,i] = (F x)_along_m + (F x)_along_n,  F = C C^T (256x32 low-rank,
// C = ortho-normalized cos/sin basis for rfft modes [0,16), exact identity).
// B=8, M=N=256, I=32, fp32.
//
// Round 13 (= R12 resubmit; R12 bench was an infra failure, source re-audited
// clean). ALL stages on tf32 tensor cores (mma.sync.m16n8k8), no smem, no
// barriers anywhere:
//   k1: D1[b,k,(n,i)] = Ct^T x   (K=256 streamed, B=x from HBM, dbl-buffered)
//   k2: D2[b,k,(m,i)] = Ct^T x'  (same, transposed access, 100% sectors)
//   k3a: out  = Cm x D1  — B frags RESIDENT in 64 regs, loop all 16 m-frags
//   k3b: out += Cn x D2  — same, RMW epilogue

#define BATCH 8
#define MDIM 256
#define NDIM 256
#define IDIM 32
#define KM 32
#define NI (NDIM * IDIM)   // 8192

__device__ float d_Ct[MDIM * KM];        // C[n][k], tf32-rounded
__device__ float d_D1[BATCH * KM * NI];  // [b][k][(n,i)]  tf32 values
__device__ float d_D2[BATCH * KM * NI];  // [b][k][(m,i)]  tf32 values

__device__ __forceinline__ uint32_t tf32_bits(float x) {
    uint32_t r;
    asm("cvt.rna.tf32.f32 %0, %1;" : "=r"(r) : "f"(x));
    return r;
}

// mma.sync m16n8k8 tf32: D += A x B (frag mapping verified passing in R11).
__device__ __forceinline__ void mma_tf32(float* d, const uint32_t* a,
                                         uint32_t b0, uint32_t b1) {
    asm volatile(
        "mma.sync.aligned.m16n8k8.row.col.f32.tf32.tf32.f32 "
        "{%0,%1,%2,%3}, {%4,%5,%6,%7}, {%8,%9}, {%0,%1,%2,%3};"
        : "+f"(d[0]), "+f"(d[1]), "+f"(d[2]), "+f"(d[3])
        : "r"(a[0]), "r"(a[1]), "r"(a[2]), "r"(a[3]), "r"(b0), "r"(b1));
}

__device__ __forceinline__ void st_tf32x2(float* p, float a, float b) {
    float2 v = make_float2(__uint_as_float(tf32_bits(a)),
                           __uint_as_float(tf32_bits(b)));
    *(float2*)p = v;
}

// ---------------------------------------------------------------------------
// Init C[n][j] (tf32-rounded). j=0: 1/16. j=1..15: cos modes. j=16..30: sin.
// ---------------------------------------------------------------------------
__global__ void init_C_kernel() {
    int idx = blockIdx.x * 256 + threadIdx.x;   // 8192
    int n = idx >> 5;
    int j = idx & 31;
    const double PI = 3.14159265358979323846;
    const double AMP = 1.4142135623730951 / 16.0;
    double v;
    if (j == 0) {
        v = 1.0 / 16.0;
    } else if (j <= 15) {
        int ph = (j * n) & 255;
        v = AMP * cos(2.0 * PI * (double)ph / 256.0);
    } else if (j <= 30) {
        int k = j - 15;
        int ph = (k * n) & 255;
        v = AMP * sin(2.0 * PI * (double)ph / 256.0);
    } else {
        v = 0.0;
    }
    d_Ct[idx] = __uint_as_float(tf32_bits((float)v));
}

// ---------------------------------------------------------------------------
// A-frag loader for the down-projections: A[row k][col m] = Ct[m*32+k].
// ---------------------------------------------------------------------------
__device__ __forceinline__ void loadA_down(uint32_t a[2][4], int kf,
                                           int gr, int tg) {
    int cA = kf * 8;
#pragma unroll
    for (int rf = 0; rf < 2; rf++) {
        int r0 = rf * 16;
        a[rf][0] = __float_as_uint(d_Ct[(cA + tg) * 32 + r0 + gr]);
        a[rf][1] = __float_as_uint(d_Ct[(cA + tg) * 32 + r0 + 8 + gr]);
        a[rf][2] = __float_as_uint(d_Ct[(cA + tg + 4) * 32 + r0 + gr]);
        a[rf][3] = __float_as_uint(d_Ct[(cA + tg + 4) * 32 + r0 + 8 + gr]);
    }
}

// ---------------------------------------------------------------------------
// K1: D1[b,k,(n,i)] = sum_m C[m,k] x[b,m,(n,i)].
// Block (ct, b), 128 thr, warp = 64 cols. M(out)=32 (2 rf), K=256 (32 kf).
// B = x rows m, cols (n,i): contiguous -> 100% sectors. Double-buffered regs.
// ---------------------------------------------------------------------------
__global__ void __launch_bounds__(128) k1_down_m(const float* __restrict__ x) {
    int t = threadIdx.x, lane = t & 31, w = t >> 5;
    int ct = blockIdx.x, b = blockIdx.y;
    int gr = lane >> 2, tg = lane & 3;
    int colbase = ct * 256 + w * 64;
    const float* Bx = x + (size_t)b * (MDIM * NI);

    float acc[2][8][4];
#pragma unroll
    for (int rf = 0; rf < 2; rf++)
#pragma unroll
        for (int cf = 0; cf < 8; cf++)
#pragma unroll
            for (int q = 0; q < 4; q++) acc[rf][cf][q] = 0.f;

    uint32_t bA[8][2], bB[8][2];

    auto loadB = [&](int kf, uint32_t (&dst)[8][2]) {
        int r0 = kf * 8 + tg;
#pragma unroll
        for (int cf = 0; cf < 8; cf++) {
            int col = colbase + cf * 8 + gr;
            dst[cf][0] = tf32_bits(__ldg(&Bx[(size_t)r0 * NI + col]));
            dst[cf][1] = tf32_bits(__ldg(&Bx[(size_t)(r0 + 4) * NI + col]));
        }
    };
    auto step = [&](int kf, uint32_t (&cur)[8][2]) {
        uint32_t a[2][4];
        loadA_down(a, kf, gr, tg);
#pragma unroll
        for (int cf = 0; cf < 8; cf++) {
            mma_tf32(acc[0][cf], a[0], cur[cf][0], cur[cf][1]);
            mma_tf32(acc[1][cf], a[1], cur[cf][0], cur[cf][1]);
        }
    };

    loadB(0, bA);
    for (int kf2 = 0; kf2 < 16; kf2++) {
        int kf = kf2 * 2;
        loadB(kf + 1, bB);
        step(kf, bA);
        if (kf + 2 < 32) loadB(kf + 2, bA);
        step(kf + 1, bB);
    }

#pragma unroll
    for (int rf = 0; rf < 2; rf++) {
        int row = rf * 16 + gr;
#pragma unroll
        for (int cf = 0; cf < 8; cf++) {
            size_t base = ((size_t)b * 32 + row) * NI + colbase + cf * 8 + 2 * tg;
            st_tf32x2(&d_D1[base], acc[rf][cf][0], acc[rf][cf][1]);
            st_tf32x2(&d_D1[base + (size_t)8 * NI], acc[rf][cf][2], acc[rf][cf][3]);
        }
    }
}

// ---------------------------------------------------------------------------
// K2: D2[b,k,(m,i)] = sum_n C[n,k] x[b,m,n,i].
// Same skeleton; B rows = n (stride 32 floats), cols (m,i). 100% sectors.
// ---------------------------------------------------------------------------
__global__ void __launch_bounds__(128) k2_down_n(const float* __restrict__ x) {
    int t = threadIdx.x, lane = t & 31, w = t >> 5;
    int ct = blockIdx.x, b = blockIdx.y;
    int gr = lane >> 2, tg = lane & 3;
    int colbase = ct * 256 + w * 64;
    const float* Bx = x + (size_t)b * (MDIM * NI);

    float acc[2][8][4];
#pragma unroll
    for (int rf = 0; rf < 2; rf++)
#pragma unroll
        for (int cf = 0; cf < 8; cf++)
#pragma unroll
            for (int q = 0; q < 4; q++) acc[rf][cf][q] = 0.f;

    uint32_t bA[8][2], bB[8][2];

    auto loadB = [&](int kf, uint32_t (&dst)[8][2]) {
        int n0 = kf * 8 + tg;
#pragma unroll
        for (int cf = 0; cf < 8; cf++) {
            int colw = colbase + cf * 8;        // 8-aligned -> one m per cf
            int m  = colw >> 5;
            int ii = (colw & 31) + gr;
            dst[cf][0] = tf32_bits(__ldg(&Bx[(size_t)m * NI + n0 * 32 + ii]));
            dst[cf][1] = tf32_bits(__ldg(&Bx[(size_t)m * NI + (n0 + 4) * 32 + ii]));
        }
    };
    auto step = [&](int kf, uint32_t (&cur)[8][2]) {
        uint32_t a[2][4];
        loadA_down(a, kf, gr, tg);
#pragma unroll
        for (int cf = 0; cf < 8; cf++) {
            mma_tf32(acc[0][cf], a[0], cur[cf][0], cur[cf][1]);
            mma_tf32(acc[1][cf], a[1], cur[cf][0], cur[cf][1]);
        }
    };

    loadB(0, bA);
    for (int kf2 = 0; kf2 < 16; kf2++) {
        int kf = kf2 * 2;
        loadB(kf + 1, bB);
        step(kf, bA);
        if (kf + 2 < 32) loadB(kf + 2, bA);
        step(kf + 1, bB);
    }

#pragma unroll
    for (int rf = 0; rf < 2; rf++) {
        int row = rf * 16 + gr;
#pragma unroll
        for (int cf = 0; cf < 8; cf++) {
            size_t base = ((size_t)b * 32 + row) * NI + colbase + cf * 8 + 2 * tg;
            st_tf32x2(&d_D2[base], acc[rf][cf][0], acc[rf][cf][1]);
            st_tf32x2(&d_D2[base + (size_t)8 * NI], acc[rf][cf][2], acc[rf][cf][3]);
        }
    }
}

// ---------------------------------------------------------------------------
// K3a: out[b][m][(n,i)] = sum_k Ct[m,k] D1[b,k,(n,i)].
// Block (ct, b), 128 thr, warp = 64 cols. B frags RESIDENT (8cf x 4kf x 2 =
// 64 regs, loaded once); loop rf = 0..15 covers all 256 m rows.
// ---------------------------------------------------------------------------
__global__ void __launch_bounds__(128) k3a_up(float* __restrict__ out) {
    int t = threadIdx.x, lane = t & 31, w = t >> 5;
    int ct = blockIdx.x, b = blockIdx.y;
    int gr = lane >> 2, tg = lane & 3;
    int colbase = ct * 256 + w * 64;

    const float* B = d_D1 + (size_t)b * 32 * NI;

    uint32_t bf[4][8][2];
#pragma unroll
    for (int kf = 0; kf < 4; kf++) {
        int r0 = kf * 8 + tg;
#pragma unroll
        for (int cf = 0; cf < 8; cf++) {
            int col = colbase + cf * 8 + gr;
            bf[kf][cf][0] = __float_as_uint(__ldg(&B[(size_t)r0 * NI + col]));
            bf[kf][cf][1] = __float_as_uint(__ldg(&B[(size_t)(r0 + 4) * NI + col]));
        }
    }

    for (int rf = 0; rf < 16; rf++) {
        int r0 = rf * 16;
        uint32_t a[4][4];
#pragma unroll
        for (int kf = 0; kf < 4; kf++) {
            int c = kf * 8 + tg;
            a[kf][0] = __float_as_uint(d_Ct[(r0 + gr) * 32 + c]);
            a[kf][1] = __float_as_uint(d_Ct[(r0 + 8 + gr) * 32 + c]);
            a[kf][2] = __float_as_uint(d_Ct[(r0 + gr) * 32 + c + 4]);
            a[kf][3] = __float_as_uint(d_Ct[(r0 + 8 + gr) * 32 + c + 4]);
        }

        float acc[8][4];
#pragma unroll
        for (int cf = 0; cf < 8; cf++)
#pragma unroll
            for (int q = 0; q < 4; q++) acc[cf][q] = 0.f;

#pragma unroll
        for (int cf = 0; cf < 8; cf++)
#pragma unroll
            for (int kf = 0; kf < 4; kf++)
                mma_tf32(acc[cf], a[kf], bf[kf][cf][0], bf[kf][cf][1]);

        int r = r0 + gr;
#pragma unroll
        for (int cf = 0; cf < 8; cf++) {
            size_t base = ((size_t)b * 256 + r) * NI + colbase + cf * 8 + 2 * tg;
            *(float2*)&out[base] = make_float2(acc[cf][0], acc[cf][1]);
            *(float2*)&out[base + (size_t)8 * NI] = make_float2(acc[cf][2], acc[cf][3]);
        }
    }
}

// ---------------------------------------------------------------------------
// K3b: out[b][m][n][i] += sum_k Ct[n,k] D2[b,k,(m,i)].  Same structure,
// rows = n, cols = (m,i); RMW scatter epilogue (out L2-hot from k3a).
// ---------------------------------------------------------------------------
__global__ void __launch_bounds__(128) k3b_up(float* __restrict__ out) {
    int t = threadIdx.x, lane = t & 31, w = t >> 5;
    int ct = blockIdx.x, b = blockIdx.y;
    int gr = lane >> 2, tg = lane & 3;
    int colbase = ct * 256 + w * 64;

    const float* B = d_D2 + (size_t)b * 32 * NI;

    uint32_t bf[4][8][2];
#pragma unroll
    for (int kf = 0; kf < 4; kf++) {
        int r0 = kf * 8 + tg;
#pragma unroll
        for (int cf = 0; cf < 8; cf++) {
            int col = colbase + cf * 8 + gr;
            bf[kf][cf][0] = __float_as_uint(__ldg(&B[(size_t)r0 * NI + col]));
            bf[kf][cf][1] = __float_as_uint(__ldg(&B[(size_t)(r0 + 4) * NI + col]));
        }
    }

    for (int rf = 0; rf < 16; rf++) {
        int r0 = rf * 16;
        uint32_t a[4][4];
#pragma unroll
        for (int kf = 0; kf < 4; kf++) {
            int c = kf * 8 + tg;
            a[kf][0] = __float_as_uint(d_Ct[(r0 + gr) * 32 + c]);
            a[kf][1] = __float_as_uint(d_Ct[(r0 + 8 + gr) * 32 + c]);
            a[kf][2] = __float_as_uint(d_Ct[(r0 + gr) * 32 + c + 4]);
            a[kf][3] = __float_as_uint(d_Ct[(r0 + 8 + gr) * 32 + c + 4]);
        }

        float acc[8][4];
#pragma unroll
        for (int cf = 0; cf < 8; cf++)
#pragma unroll
            for (int q = 0; q < 4; q++) acc[cf][q] = 0.f;

#pragma unroll
        for (int cf = 0; cf < 8; cf++)
#pragma unroll
            for (int kf = 0; kf < 4; kf++)
                mma_tf32(acc[cf], a[kf], bf[kf][cf][0], bf[kf][cf][1]);

        // rows = n, cols = (m,i): out[b][m][n][i]
#pragma unroll
        for (int cf = 0; cf < 8; cf++) {
            int cb = colbase + cf * 8;        // 8-aligned, one m per cf
            int m  = cb >> 5;
            int ib = (cb & 31) + 2 * tg;
            int n  = r0 + gr;
            size_t ad = ((size_t)b * 256 + m) * NI + n * 32 + ib;
            float2 o0 = *(float2*)&out[ad];
            o0.x += acc[cf][0];
            o0.y += acc[cf][1];
            *(float2*)&out[ad] = o0;
            size_t ad2 = ad + 8 * 32;         // row n+8
            float2 o1 = *(float2*)&out[ad2];
            o1.x += acc[cf][2];
            o1.y += acc[cf][3];
            *(float2*)&out[ad2] = o1;
        }
    }
}

// ---------------------------------------------------------------------------
extern "C" void kernel_launch(void* const* d_in, const int* in_sizes, int n_in,
                              void* d_out, int out_size) {
    const float* x = (const float*)d_in[0];
    float* out = (float*)d_out;

    init_C_kernel<<<32, 256>>>();
    k1_down_m<<<dim3(32, 8), 128>>>(x);
    k2_down_n<<<dim3(32, 8), 128>>>(x);
    k3a_up<<<dim3(32, 8), 128>>>(out);
    k3b_up<<<dim3(32, 8), 128>>>(out);
}

// round 14
// speedup vs baseline: 1.1412x; 1.0463x over previous
#include <cuda_runtime.h>
#include <cstdint>

// Filtering_72773925863700
// out[b,m,n,i] = (F x)_along_m + (F x)_along_n,  F = C C^T (256x32 low-rank,
// C = ortho-normalized cos/sin basis for rfft modes [0,16), exact identity).
// B=8, M=N=256, I=32, fp32.
//
// Round 14: best measured pieces composed.
//   k1/k2: scalar fp32 bulk-async (R11 versions — tensor k1/k2 was scalar-LDG
//          issue-bound), tf32-rounded stores, D2 in [b][k][(m,i)].
//   k3a/k3b: tf32 mma with resident B-frags; 16-rf loop SPLIT across 4 blocks
//          (grid 32x4x8=1024) to fix occ=10.9%/issue=5.7% from R13.

#define BATCH 8
#define MDIM 256
#define NDIM 256
#define IDIM 32
#define KM 32
#define NI (NDIM * IDIM)   // 8192

__device__ float d_C[MDIM * KM];         // C[n][k] fp32 (k1/k2 staging)
__device__ float d_Ct[MDIM * KM];        // C[n][k] tf32-rounded (mma A)
__device__ float d_D1[BATCH * KM * NI];  // [b][k][(n,i)]  tf32 values
__device__ float d_D2[BATCH * KM * NI];  // [b][k][(m,i)]  tf32 values

union F4U { float4 f4; uint64_t u[2]; float f[4]; };

__device__ __forceinline__ uint64_t pack2(float c) {
    uint64_t r;
    asm("mov.b64 %0, {%1, %1};" : "=l"(r) : "f"(c));
    return r;
}
__device__ __forceinline__ void fma2(uint64_t& acc, uint64_t a, uint64_t b) {
    asm("fma.rn.f32x2 %0, %1, %2, %0;" : "+l"(acc) : "l"(a), "l"(b));
}
__device__ __forceinline__ uint32_t tf32_bits(float x) {
    uint32_t r;
    asm("cvt.rna.tf32.f32 %0, %1;" : "=r"(r) : "f"(x));
    return r;
}
__device__ __forceinline__ uint32_t sm_addr(const void* p) {
    uint32_t a;
    asm("{ .reg .u64 t; cvta.to.shared.u64 t, %1; cvt.u32.u64 %0, t; }"
        : "=r"(a) : "l"(p));
    return a;
}
__device__ __forceinline__ void mbar_init(uint32_t mbar, uint32_t count) {
    asm volatile("mbarrier.init.shared.b64 [%0], %1;" :: "r"(mbar), "r"(count) : "memory");
}
__device__ __forceinline__ void mbar_expect(uint32_t mbar, uint32_t bytes) {
    asm volatile("mbarrier.arrive.expect_tx.shared.b64 _, [%0], %1;"
                 :: "r"(mbar), "r"(bytes) : "memory");
}
__device__ __forceinline__ void bulk_g2s(uint32_t dst, const void* src,
                                         uint32_t bytes, uint32_t mbar) {
    asm volatile(
        "cp.async.bulk.shared::cta.global.mbarrier::complete_tx::bytes [%0], [%1], %2, [%3];"
        :: "r"(dst), "l"(src), "r"(bytes), "r"(mbar) : "memory");
}
__device__ __forceinline__ void mbar_wait(uint32_t mbar, uint32_t parity) {
    asm volatile(
        "{\n\t"
        ".reg .pred P1;\n\t"
        "WAIT_LOOP_%=:\n\t"
        "mbarrier.try_wait.parity.acquire.cta.shared::cta.b64 P1, [%0], %1;\n\t"
        "@P1 bra.uni WAIT_DONE_%=;\n\t"
        "bra.uni WAIT_LOOP_%=;\n\t"
        "WAIT_DONE_%=:\n\t"
        "}"
        :: "r"(mbar), "r"(parity) : "memory");
}
// mma.sync m16n8k8 tf32: D += A x B (mapping verified in R11/R13).
__device__ __forceinline__ void mma_tf32(float* d, const uint32_t* a,
                                         uint32_t b0, uint32_t b1) {
    asm volatile(
        "mma.sync.aligned.m16n8k8.row.col.f32.tf32.tf32.f32 "
        "{%0,%1,%2,%3}, {%4,%5,%6,%7}, {%8,%9}, {%0,%1,%2,%3};"
        : "+f"(d[0]), "+f"(d[1]), "+f"(d[2]), "+f"(d[3])
        : "r"(a[0]), "r"(a[1]), "r"(a[2]), "r"(a[3]), "r"(b0), "r"(b1));
}
__device__ __forceinline__ void st_tf32x4(float* p, const float* v) {
    F4U o;
    o.f[0] = __uint_as_float(tf32_bits(v[0]));
    o.f[1] = __uint_as_float(tf32_bits(v[1]));
    o.f[2] = __uint_as_float(tf32_bits(v[2]));
    o.f[3] = __uint_as_float(tf32_bits(v[3]));
    *(float4*)p = o.f4;
}

// ---------------------------------------------------------------------------
// Init C[n][j] fp32 + tf32 copy.
// ---------------------------------------------------------------------------
__global__ void init_C_kernel() {
    int idx = blockIdx.x * 256 + threadIdx.x;   // 8192
    int n = idx >> 5;
    int j = idx & 31;
    const double PI = 3.14159265358979323846;
    const double AMP = 1.4142135623730951 / 16.0;
    double v;
    if (j == 0) {
        v = 1.0 / 16.0;
    } else if (j <= 15) {
        int ph = (j * n) & 255;
        v = AMP * cos(2.0 * PI * (double)ph / 256.0);
    } else if (j <= 30) {
        int k = j - 15;
        int ph = (k * n) & 255;
        v = AMP * sin(2.0 * PI * (double)ph / 256.0);
    } else {
        v = 0.0;
    }
    float f = (float)v;
    d_C[idx]  = f;
    d_Ct[idx] = __uint_as_float(tf32_bits(f));
}

// ---------------------------------------------------------------------------
// K1: D1[b,k,(n,i)] = sum_m C[m,k] x[b,m,(n,i)].  Scalar fp32, bulk-async.
// Block (jt, b), 128 thr: ko=t>>5 (8 k), jq=t&31 (quads at jq*4, 128+jq*4).
// ---------------------------------------------------------------------------
__global__ void __launch_bounds__(128) k1_down_m(const float* __restrict__ x) {
    __shared__ __align__(128) float xs[2][8 * 256];
    __shared__ __align__(128) float cs[2][8 * 32];
    __shared__ __align__(8) uint64_t mbar[2];

    int t  = threadIdx.x;
    int b  = blockIdx.y;
    int j0 = blockIdx.x * 256;
    int jq = t & 31;
    int ko = t >> 5;

    const float* xb = x + (size_t)b * (MDIM * NI);
    uint32_t mb0 = sm_addr(&mbar[0]);
    uint32_t mb1 = sm_addr(&mbar[1]);

    if (t == 0) { mbar_init(mb0, 1); mbar_init(mb1, 1); }
    __syncthreads();

    const uint32_t CHUNK_BYTES = 8 * 256 * 4 + 8 * 32 * 4;

    auto issue = [&](int mc, int s) {
        uint32_t mb = s ? mb1 : mb0;
        mbar_expect(mb, CHUNK_BYTES);
#pragma unroll
        for (int mm = 0; mm < 8; mm++)
            bulk_g2s(sm_addr(&xs[s][mm * 256]),
                     &xb[(size_t)(mc * 8 + mm) * NI + j0], 1024, mb);
        bulk_g2s(sm_addr(&cs[s][0]), &d_C[mc * 8 * 32], 1024, mb);
    };

    uint64_t acc[8][4];
#pragma unroll
    for (int a = 0; a < 8; a++)
#pragma unroll
        for (int q = 0; q < 4; q++) acc[a][q] = 0ull;

    if (t == 0) issue(0, 0);
    for (int mc = 0; mc < 32; mc++) {
        int s = mc & 1;
        if (mc + 1 < 32) {
            __syncthreads();
            if (t == 0) issue(mc + 1, s ^ 1);
        }
        mbar_wait(s ? mb1 : mb0, (mc >> 1) & 1);

        const float* xsb = xs[s];
        const float* csb = cs[s];
#pragma unroll
        for (int mm = 0; mm < 8; mm++) {
            F4U x0; x0.f4 = *(const float4*)&xsb[mm * 256 + jq * 4];
            F4U x1; x1.f4 = *(const float4*)&xsb[mm * 256 + 128 + jq * 4];
            F4U c0; c0.f4 = *(const float4*)&csb[mm * 32 + ko * 8];
            F4U c1; c1.f4 = *(const float4*)&csb[mm * 32 + ko * 8 + 4];
            float cv[8] = {c0.f[0], c0.f[1], c0.f[2], c0.f[3],
                           c1.f[0], c1.f[1], c1.f[2], c1.f[3]};
#pragma unroll
            for (int a = 0; a < 8; a++) {
                uint64_t cp = pack2(cv[a]);
                fma2(acc[a][0], cp, x0.u[0]);
                fma2(acc[a][1], cp, x0.u[1]);
                fma2(acc[a][2], cp, x1.u[0]);
                fma2(acc[a][3], cp, x1.u[1]);
            }
        }
    }

#pragma unroll
    for (int a = 0; a < 8; a++) {
        int k = ko * 8 + a;
        F4U v0; v0.u[0] = acc[a][0]; v0.u[1] = acc[a][1];
        F4U v1; v1.u[0] = acc[a][2]; v1.u[1] = acc[a][3];
        st_tf32x4(&d_D1[((size_t)b * 32 + k) * NI + j0 + jq * 4], v0.f);
        st_tf32x4(&d_D1[((size_t)b * 32 + k) * NI + j0 + 128 + jq * 4], v1.f);
    }
}

// ---------------------------------------------------------------------------
// K2: D2[b,k,(m,i)] = sum_n C[n,k] x[b,m,n,i].  Scalar fp32, bulk-async.
// Block (mt of 8 m, b), 256 thr: kq=t&3 (8 k), iq=(t>>2)&7 (4 i), ml=t>>5.
// ---------------------------------------------------------------------------
__global__ void __launch_bounds__(256) k2_down_n(const float* __restrict__ x) {
    __shared__ __align__(128) float zs[2][8 * 16 * 32];
    __shared__ __align__(128) float ch[2][16 * 32];
    __shared__ __align__(8) uint64_t mbar[2];

    int t  = threadIdx.x;
    int b  = blockIdx.y;
    int m0 = blockIdx.x * 8;
    int kq = t & 3;
    int iq = (t >> 2) & 7;
    int ml = t >> 5;

    const float* xb = x + (size_t)b * (MDIM * NI) + (size_t)m0 * NI;
    uint32_t mb0 = sm_addr(&mbar[0]);
    uint32_t mb1 = sm_addr(&mbar[1]);

    if (t == 0) { mbar_init(mb0, 1); mbar_init(mb1, 1); }
    __syncthreads();

    const uint32_t CHUNK_BYTES = 8 * 16 * 32 * 4 + 16 * 32 * 4;

    auto issue = [&](int nc, int s) {
        uint32_t mb = s ? mb1 : mb0;
        mbar_expect(mb, CHUNK_BYTES);
#pragma unroll
        for (int m2 = 0; m2 < 8; m2++)
            bulk_g2s(sm_addr(&zs[s][m2 * 16 * 32]),
                     &xb[(size_t)m2 * NI + nc * 16 * 32], 2048, mb);
        bulk_g2s(sm_addr(&ch[s][0]), &d_C[nc * 16 * 32], 2048, mb);
    };

    uint64_t acc[8][2];
#pragma unroll
    for (int kk = 0; kk < 8; kk++) { acc[kk][0] = 0ull; acc[kk][1] = 0ull; }

    if (t == 0) issue(0, 0);
    for (int nc = 0; nc < 16; nc++) {
        int s = nc & 1;
        if (nc + 1 < 16) {
            __syncthreads();
            if (t == 0) issue(nc + 1, s ^ 1);
        }
        mbar_wait(s ? mb1 : mb0, (nc >> 1) & 1);

        const float* zb = zs[s];
        const float* cb = ch[s];
#pragma unroll
        for (int nn = 0; nn < 16; nn++) {
            F4U z; z.f4 = *(const float4*)&zb[(ml * 16 + nn) * 32 + iq * 4];
            F4U c0; c0.f4 = *(const float4*)&cb[nn * 32 + kq * 8];
            F4U c1; c1.f4 = *(const float4*)&cb[nn * 32 + kq * 8 + 4];
            float cv[8] = {c0.f[0], c0.f[1], c0.f[2], c0.f[3],
                           c1.f[0], c1.f[1], c1.f[2], c1.f[3]};
#pragma unroll
            for (int kk = 0; kk < 8; kk++) {
                uint64_t cp = pack2(cv[kk]);
                fma2(acc[kk][0], cp, z.u[0]);
                fma2(acc[kk][1], cp, z.u[1]);
            }
        }
    }

#pragma unroll
    for (int kk = 0; kk < 8; kk++) {
        int k = kq * 8 + kk;
        F4U v; v.u[0] = acc[kk][0]; v.u[1] = acc[kk][1];
        // layout [b][k][(m,i)]
        st_tf32x4(&d_D2[((size_t)b * 32 + k) * NI + (m0 + ml) * 32 + iq * 4], v.f);
    }
}

// ---------------------------------------------------------------------------
// K3a: out[b][m][(n,i)] = sum_k Ct[m,k] D1[b,k,(n,i)].
// Grid (ct=32, rs=4, b=8), 128 thr. B frags resident; each block does 4 rf.
// ---------------------------------------------------------------------------
__global__ void __launch_bounds__(128) k3a_up(float* __restrict__ out) {
    int t = threadIdx.x, lane = t & 31, w = t >> 5;
    int ct = blockIdx.x, rs = blockIdx.y, b = blockIdx.z;
    int gr = lane >> 2, tg = lane & 3;
    int colbase = ct * 256 + w * 64;

    const float* B = d_D1 + (size_t)b * 32 * NI;

    uint32_t bf[4][8][2];
#pragma unroll
    for (int kf = 0; kf < 4; kf++) {
        int r0 = kf * 8 + tg;
#pragma unroll
        for (int cf = 0; cf < 8; cf++) {
            int col = colbase + cf * 8 + gr;
            bf[kf][cf][0] = __float_as_uint(__ldg(&B[(size_t)r0 * NI + col]));
            bf[kf][cf][1] = __float_as_uint(__ldg(&B[(size_t)(r0 + 4) * NI + col]));
        }
    }

#pragma unroll
    for (int rr = 0; rr < 4; rr++) {
        int rf = rs * 4 + rr;
        int r0 = rf * 16;
        uint32_t a[4][4];
#pragma unroll
        for (int kf = 0; kf < 4; kf++) {
            int c = kf * 8 + tg;
            a[kf][0] = __float_as_uint(d_Ct[(r0 + gr) * 32 + c]);
            a[kf][1] = __float_as_uint(d_Ct[(r0 + 8 + gr) * 32 + c]);
            a[kf][2] = __float_as_uint(d_Ct[(r0 + gr) * 32 + c + 4]);
            a[kf][3] = __float_as_uint(d_Ct[(r0 + 8 + gr) * 32 + c + 4]);
        }

        float acc[8][4];
#pragma unroll
        for (int cf = 0; cf < 8; cf++)
#pragma unroll
            for (int q = 0; q < 4; q++) acc[cf][q] = 0.f;

#pragma unroll
        for (int cf = 0; cf < 8; cf++)
#pragma unroll
            for (int kf = 0; kf < 4; kf++)
                mma_tf32(acc[cf], a[kf], bf[kf][cf][0], bf[kf][cf][1]);

        int r = r0 + gr;
#pragma unroll
        for (int cf = 0; cf < 8; cf++) {
            size_t base = ((size_t)b * 256 + r) * NI + colbase + cf * 8 + 2 * tg;
            *(float2*)&out[base] = make_float2(acc[cf][0], acc[cf][1]);
            *(float2*)&out[base + (size_t)8 * NI] = make_float2(acc[cf][2], acc[cf][3]);
        }
    }
}

// ---------------------------------------------------------------------------
// K3b: out[b][m][n][i] += sum_k Ct[n,k] D2[b,k,(m,i)].  Same split; RMW.
// ---------------------------------------------------------------------------
__global__ void __launch_bounds__(128) k3b_up(float* __restrict__ out) {
    int t = threadIdx.x, lane = t & 31, w = t >> 5;
    int ct = blockIdx.x, rs = blockIdx.y, b = blockIdx.z;
    int gr = lane >> 2, tg = lane & 3;
    int colbase = ct * 256 + w * 64;

    const float* B = d_D2 + (size_t)b * 32 * NI;

    uint32_t bf[4][8][2];
#pragma unroll
    for (int kf = 0; kf < 4; kf++) {
        int r0 = kf * 8 + tg;
#pragma unroll
        for (int cf = 0; cf < 8; cf++) {
            int col = colbase + cf * 8 + gr;
            bf[kf][cf][0] = __float_as_uint(__ldg(&B[(size_t)r0 * NI + col]));
            bf[kf][cf][1] = __float_as_uint(__ldg(&B[(size_t)(r0 + 4) * NI + col]));
        }
    }

#pragma unroll
    for (int rr = 0; rr < 4; rr++) {
        int rf = rs * 4 + rr;
        int r0 = rf * 16;
        uint32_t a[4][4];
#pragma unroll
        for (int kf = 0; kf < 4; kf++) {
            int c = kf * 8 + tg;
            a[kf][0] = __float_as_uint(d_Ct[(r0 + gr) * 32 + c]);
            a[kf][1] = __float_as_uint(d_Ct[(r0 + 8 + gr) * 32 + c]);
            a[kf][2] = __float_as_uint(d_Ct[(r0 + gr) * 32 + c + 4]);
            a[kf][3] = __float_as_uint(d_Ct[(r0 + 8 + gr) * 32 + c + 4]);
        }

        float acc[8][4];
#pragma unroll
        for (int cf = 0; cf < 8; cf++)
#pragma unroll
            for (int q = 0; q < 4; q++) acc[cf][q] = 0.f;

#pragma unroll
        for (int cf = 0; cf < 8; cf++)
#pragma unroll
            for (int kf = 0; kf < 4; kf++)
                mma_tf32(acc[cf], a[kf], bf[kf][cf][0], bf[kf][cf][1]);

        // rows = n, cols = (m,i): out[b][m][n][i]
#pragma unroll
        for (int cf = 0; cf < 8; cf++) {
            int cb = colbase + cf * 8;        // 8-aligned, one m per cf
            int m  = cb >> 5;
            int ib = (cb & 31) + 2 * tg;
            int n  = r0 + gr;
            size_t ad = ((size_t)b * 256 + m) * NI + n * 32 + ib;
            float2 o0 = *(float2*)&out[ad];
            o0.x += acc[cf][0];
            o0.y += acc[cf][1];
            *(float2*)&out[ad] = o0;
            size_t ad2 = ad + 8 * 32;         // row n+8
            float2 o1 = *(float2*)&out[ad2];
            o1.x += acc[cf][2];
            o1.y += acc[cf][3];
            *(float2*)&out[ad2] = o1;
        }
    }
}

// ---------------------------------------------------------------------------
extern "C" void kernel_launch(void* const* d_in, const int* in_sizes, int n_in,
                              void* d_out, int out_size) {
    const float* x = (const float*)d_in[0];
    float* out = (float*)d_out;

    init_C_kernel<<<32, 256>>>();
    k1_down_m<<<dim3(32, 8), 128>>>(x);
    k2_down_n<<<dim3(32, 8), 256>>>(x);
    k3a_up<<<dim3(32, 4, 8), 128>>>(out);
    k3b_up<<<dim3(32, 4, 8), 128>>>(out);
}

// round 15
// speedup vs baseline: 1.2857x; 1.1267x over previous
#include <cuda_runtime.h>
#include <cstdint>

// Filtering_72773925863700
// out[b,m,n,i] = (F x)_along_m + (F x)_along_n,  F = C C^T (256x32 low-rank).
// B=8, M=N=256, I=32, fp32.
//
// Round 15:
//   - A-frags for the mma kernels PRECOMPUTED in fragment order (d_Afrag):
//     one LDG.128 per (rf,kf) instead of 16 scattered scalar LDGs (the
//     measured L1-wavefront dominator in R14's k3a).
//   - k1/k2 grids doubled (tiles halved) for TMA latency hiding.
//   - k3a/k3b otherwise as R14 (resident B-frags, rs=4 split).

#define BATCH 8
#define MDIM 256
#define NDIM 256
#define IDIM 32
#define KM 32
#define NI (NDIM * IDIM)   // 8192

__device__ float d_C[MDIM * KM];          // C[n][k] fp32 (k1/k2 staging)
__device__ float d_Ct[MDIM * KM];         // C[n][k] tf32-rounded
__device__ float d_Afrag[16 * 4 * 32 * 4]; // [rf][kf][lane][4] mma A frags
__device__ float d_D1[BATCH * KM * NI];   // [b][k][(n,i)]  tf32 values
__device__ float d_D2[BATCH * KM * NI];   // [b][k][(m,i)]  tf32 values

union F4U { float4 f4; uint64_t u[2]; float f[4]; };
union U4F { uint4 u4; uint32_t u[4]; };

__device__ __forceinline__ uint64_t pack2(float c) {
    uint64_t r;
    asm("mov.b64 %0, {%1, %1};" : "=l"(r) : "f"(c));
    return r;
}
__device__ __forceinline__ void fma2(uint64_t& acc, uint64_t a, uint64_t b) {
    asm("fma.rn.f32x2 %0, %1, %2, %0;" : "+l"(acc) : "l"(a), "l"(b));
}
__device__ __forceinline__ uint32_t tf32_bits(float x) {
    uint32_t r;
    asm("cvt.rna.tf32.f32 %0, %1;" : "=r"(r) : "f"(x));
    return r;
}
__device__ __forceinline__ uint32_t sm_addr(const void* p) {
    uint32_t a;
    asm("{ .reg .u64 t; cvta.to.shared.u64 t, %1; cvt.u32.u64 %0, t; }"
        : "=r"(a) : "l"(p));
    return a;
}
__device__ __forceinline__ void mbar_init(uint32_t mbar, uint32_t count) {
    asm volatile("mbarrier.init.shared.b64 [%0], %1;" :: "r"(mbar), "r"(count) : "memory");
}
__device__ __forceinline__ void mbar_expect(uint32_t mbar, uint32_t bytes) {
    asm volatile("mbarrier.arrive.expect_tx.shared.b64 _, [%0], %1;"
                 :: "r"(mbar), "r"(bytes) : "memory");
}
__device__ __forceinline__ void bulk_g2s(uint32_t dst, const void* src,
                                         uint32_t bytes, uint32_t mbar) {
    asm volatile(
        "cp.async.bulk.shared::cta.global.mbarrier::complete_tx::bytes [%0], [%1], %2, [%3];"
        :: "r"(dst), "l"(src), "r"(bytes), "r"(mbar) : "memory");
}
__device__ __forceinline__ void mbar_wait(uint32_t mbar, uint32_t parity) {
    asm volatile(
        "{\n\t"
        ".reg .pred P1;\n\t"
        "WAIT_LOOP_%=:\n\t"
        "mbarrier.try_wait.parity.acquire.cta.shared::cta.b64 P1, [%0], %1;\n\t"
        "@P1 bra.uni WAIT_DONE_%=;\n\t"
        "bra.uni WAIT_LOOP_%=;\n\t"
        "WAIT_DONE_%=:\n\t"
        "}"
        :: "r"(mbar), "r"(parity) : "memory");
}
// mma.sync m16n8k8 tf32: D += A x B (mapping verified in R11/R13/R14).
__device__ __forceinline__ void mma_tf32(float* d, const uint32_t* a,
                                         uint32_t b0, uint32_t b1) {
    asm volatile(
        "mma.sync.aligned.m16n8k8.row.col.f32.tf32.tf32.f32 "
        "{%0,%1,%2,%3}, {%4,%5,%6,%7}, {%8,%9}, {%0,%1,%2,%3};"
        : "+f"(d[0]), "+f"(d[1]), "+f"(d[2]), "+f"(d[3])
        : "r"(a[0]), "r"(a[1]), "r"(a[2]), "r"(a[3]), "r"(b0), "r"(b1));
}
__device__ __forceinline__ void st_tf32x4(float* p, const float* v) {
    F4U o;
    o.f[0] = __uint_as_float(tf32_bits(v[0]));
    o.f[1] = __uint_as_float(tf32_bits(v[1]));
    o.f[2] = __uint_as_float(tf32_bits(v[2]));
    o.f[3] = __uint_as_float(tf32_bits(v[3]));
    *(float4*)p = o.f4;
}

// ---------------------------------------------------------------------------
// Init C (fp32 + tf32).
// ---------------------------------------------------------------------------
__global__ void init_C_kernel() {
    int idx = blockIdx.x * 256 + threadIdx.x;   // 8192
    int n = idx >> 5;
    int j = idx & 31;
    const double PI = 3.14159265358979323846;
    const double AMP = 1.4142135623730951 / 16.0;
    double v;
    if (j == 0) {
        v = 1.0 / 16.0;
    } else if (j <= 15) {
        int ph = (j * n) & 255;
        v = AMP * cos(2.0 * PI * (double)ph / 256.0);
    } else if (j <= 30) {
        int k = j - 15;
        int ph = (k * n) & 255;
        v = AMP * sin(2.0 * PI * (double)ph / 256.0);
    } else {
        v = 0.0;
    }
    float f = (float)v;
    d_C[idx]  = f;
    d_Ct[idx] = __uint_as_float(tf32_bits(f));
}

// Pack Ct into mma A-fragment order: [rf][kf][lane] -> float4 (a0,a1,a2,a3).
__global__ void init_A_kernel() {
    int idx = blockIdx.x * 256 + threadIdx.x;   // 2048 = 16*4*32
    int lane = idx & 31;
    int kf = (idx >> 5) & 3;
    int rf = idx >> 7;
    int gr = lane >> 2, tg = lane & 3;
    int r0 = rf * 16, c = kf * 8 + tg;
    float4 v;
    v.x = d_Ct[(r0 + gr) * 32 + c];
    v.y = d_Ct[(r0 + 8 + gr) * 32 + c];
    v.z = d_Ct[(r0 + gr) * 32 + c + 4];
    v.w = d_Ct[(r0 + 8 + gr) * 32 + c + 4];
    ((float4*)d_Afrag)[idx] = v;
}

// ---------------------------------------------------------------------------
// K1: D1[b,k,(n,i)] = sum_m C[m,k] x[b,m,(n,i)].  Scalar fp32, bulk-async.
// Grid (64, 8), 128 thr. Tile [32k x 128j]; 16 chunks of 16 m.
// Thread: ko=t>>5 (8 k), jq=t&31 (one float4 of j).
// ---------------------------------------------------------------------------
__global__ void __launch_bounds__(128) k1_down_m(const float* __restrict__ x) {
    __shared__ __align__(128) float xs[2][16 * 128];   // 8 KB each
    __shared__ __align__(128) float cs[2][16 * 32];    // 2 KB each
    __shared__ __align__(8) uint64_t mbar[2];

    int t  = threadIdx.x;
    int b  = blockIdx.y;
    int j0 = blockIdx.x * 128;
    int jq = t & 31;
    int ko = t >> 5;

    const float* xb = x + (size_t)b * (MDIM * NI);
    uint32_t mb0 = sm_addr(&mbar[0]);
    uint32_t mb1 = sm_addr(&mbar[1]);

    if (t == 0) { mbar_init(mb0, 1); mbar_init(mb1, 1); }
    __syncthreads();

    const uint32_t CHUNK_BYTES = 16 * 128 * 4 + 16 * 32 * 4;   // 10240

    auto issue = [&](int mc, int s) {
        uint32_t mb = s ? mb1 : mb0;
        mbar_expect(mb, CHUNK_BYTES);
#pragma unroll
        for (int mm = 0; mm < 16; mm++)
            bulk_g2s(sm_addr(&xs[s][mm * 128]),
                     &xb[(size_t)(mc * 16 + mm) * NI + j0], 512, mb);
        bulk_g2s(sm_addr(&cs[s][0]), &d_C[mc * 16 * 32], 2048, mb);
    };

    uint64_t acc[8][2];
#pragma unroll
    for (int a = 0; a < 8; a++) { acc[a][0] = 0ull; acc[a][1] = 0ull; }

    if (t == 0) issue(0, 0);
    for (int mc = 0; mc < 16; mc++) {
        int s = mc & 1;
        if (mc + 1 < 16) {
            __syncthreads();
            if (t == 0) issue(mc + 1, s ^ 1);
        }
        mbar_wait(s ? mb1 : mb0, (mc >> 1) & 1);

        const float* xsb = xs[s];
        const float* csb = cs[s];
#pragma unroll
        for (int mm = 0; mm < 16; mm++) {
            F4U xv; xv.f4 = *(const float4*)&xsb[mm * 128 + jq * 4];
            F4U c0; c0.f4 = *(const float4*)&csb[mm * 32 + ko * 8];
            F4U c1; c1.f4 = *(const float4*)&csb[mm * 32 + ko * 8 + 4];
            float cv[8] = {c0.f[0], c0.f[1], c0.f[2], c0.f[3],
                           c1.f[0], c1.f[1], c1.f[2], c1.f[3]};
#pragma unroll
            for (int a = 0; a < 8; a++) {
                uint64_t cp = pack2(cv[a]);
                fma2(acc[a][0], cp, xv.u[0]);
                fma2(acc[a][1], cp, xv.u[1]);
            }
        }
    }

#pragma unroll
    for (int a = 0; a < 8; a++) {
        int k = ko * 8 + a;
        F4U v; v.u[0] = acc[a][0]; v.u[1] = acc[a][1];
        st_tf32x4(&d_D1[((size_t)b * 32 + k) * NI + j0 + jq * 4], v.f);
    }
}

// ---------------------------------------------------------------------------
// K2: D2[b,k,(m,i)] = sum_n C[n,k] x[b,m,n,i].  Scalar fp32, bulk-async.
// Grid (64, 8), 128 thr. Tile 4 m; 16 chunks of 16 n.
// Thread: kq=t&3 (8 k), iq=(t>>2)&7 (4 i), ml=t>>5 (warp-uniform m).
// ---------------------------------------------------------------------------
__global__ void __launch_bounds__(128) k2_down_n(const float* __restrict__ x) {
    __shared__ __align__(128) float zs[2][4 * 16 * 32];   // 8 KB each
    __shared__ __align__(128) float ch[2][16 * 32];       // 2 KB each
    __shared__ __align__(8) uint64_t mbar[2];

    int t  = threadIdx.x;
    int b  = blockIdx.y;
    int m0 = blockIdx.x * 4;
    int kq = t & 3;
    int iq = (t >> 2) & 7;
    int ml = t >> 5;   // 0..3

    const float* xb = x + (size_t)b * (MDIM * NI) + (size_t)m0 * NI;
    uint32_t mb0 = sm_addr(&mbar[0]);
    uint32_t mb1 = sm_addr(&mbar[1]);

    if (t == 0) { mbar_init(mb0, 1); mbar_init(mb1, 1); }
    __syncthreads();

    const uint32_t CHUNK_BYTES = 4 * 16 * 32 * 4 + 16 * 32 * 4;   // 10240

    auto issue = [&](int nc, int s) {
        uint32_t mb = s ? mb1 : mb0;
        mbar_expect(mb, CHUNK_BYTES);
#pragma unroll
        for (int m2 = 0; m2 < 4; m2++)
            bulk_g2s(sm_addr(&zs[s][m2 * 16 * 32]),
                     &xb[(size_t)m2 * NI + nc * 16 * 32], 2048, mb);
        bulk_g2s(sm_addr(&ch[s][0]), &d_C[nc * 16 * 32], 2048, mb);
    };

    uint64_t acc[8][2];
#pragma unroll
    for (int kk = 0; kk < 8; kk++) { acc[kk][0] = 0ull; acc[kk][1] = 0ull; }

    if (t == 0) issue(0, 0);
    for (int nc = 0; nc < 16; nc++) {
        int s = nc & 1;
        if (nc + 1 < 16) {
            __syncthreads();
            if (t == 0) issue(nc + 1, s ^ 1);
        }
        mbar_wait(s ? mb1 : mb0, (nc >> 1) & 1);

        const float* zb = zs[s];
        const float* cb = ch[s];
#pragma unroll
        for (int nn = 0; nn < 16; nn++) {
            F4U z; z.f4 = *(const float4*)&zb[(ml * 16 + nn) * 32 + iq * 4];
            F4U c0; c0.f4 = *(const float4*)&cb[nn * 32 + kq * 8];
            F4U c1; c1.f4 = *(const float4*)&cb[nn * 32 + kq * 8 + 4];
            float cv[8] = {c0.f[0], c0.f[1], c0.f[2], c0.f[3],
                           c1.f[0], c1.f[1], c1.f[2], c1.f[3]};
#pragma unroll
            for (int kk = 0; kk < 8; kk++) {
                uint64_t cp = pack2(cv[kk]);
                fma2(acc[kk][0], cp, z.u[0]);
                fma2(acc[kk][1], cp, z.u[1]);
            }
        }
    }

#pragma unroll
    for (int kk = 0; kk < 8; kk++) {
        int k = kq * 8 + kk;
        F4U v; v.u[0] = acc[kk][0]; v.u[1] = acc[kk][1];
        st_tf32x4(&d_D2[((size_t)b * 32 + k) * NI + (m0 + ml) * 32 + iq * 4], v.f);
    }
}

// ---------------------------------------------------------------------------
// K3a: out[b][m][(n,i)] = sum_k Ct[m,k] D1[b,k,(n,i)].
// Grid (ct=32, rs=4, b=8), 128 thr. B frags resident; A via one LDG.128
// per (rf,kf) from d_Afrag; each block does 4 rf.
// ---------------------------------------------------------------------------
__global__ void __launch_bounds__(128) k3a_up(float* __restrict__ out) {
    int t = threadIdx.x, lane = t & 31, w = t >> 5;
    int ct = blockIdx.x, rs = blockIdx.y, b = blockIdx.z;
    int gr = lane >> 2, tg = lane & 3;
    int colbase = ct * 256 + w * 64;

    const float* B = d_D1 + (size_t)b * 32 * NI;
    const uint4* Af = (const uint4*)d_Afrag;

    uint32_t bf[4][8][2];
#pragma unroll
    for (int kf = 0; kf < 4; kf++) {
        int r0 = kf * 8 + tg;
#pragma unroll
        for (int cf = 0; cf < 8; cf++) {
            int col = colbase + cf * 8 + gr;
            bf[kf][cf][0] = __float_as_uint(__ldg(&B[(size_t)r0 * NI + col]));
            bf[kf][cf][1] = __float_as_uint(__ldg(&B[(size_t)(r0 + 4) * NI + col]));
        }
    }

#pragma unroll
    for (int rr = 0; rr < 4; rr++) {
        int rf = rs * 4 + rr;
        int r0 = rf * 16;

        U4F a[4];
#pragma unroll
        for (int kf = 0; kf < 4; kf++)
            a[kf].u4 = __ldg(&Af[(rf * 4 + kf) * 32 + lane]);

        float acc[8][4];
#pragma unroll
        for (int cf = 0; cf < 8; cf++)
#pragma unroll
            for (int q = 0; q < 4; q++) acc[cf][q] = 0.f;

#pragma unroll
        for (int cf = 0; cf < 8; cf++)
#pragma unroll
            for (int kf = 0; kf < 4; kf++)
                mma_tf32(acc[cf], a[kf].u, bf[kf][cf][0], bf[kf][cf][1]);

        int r = r0 + gr;
#pragma unroll
        for (int cf = 0; cf < 8; cf++) {
            size_t base = ((size_t)b * 256 + r) * NI + colbase + cf * 8 + 2 * tg;
            *(float2*)&out[base] = make_float2(acc[cf][0], acc[cf][1]);
            *(float2*)&out[base + (size_t)8 * NI] = make_float2(acc[cf][2], acc[cf][3]);
        }
    }
}

// ---------------------------------------------------------------------------
// K3b: out[b][m][n][i] += sum_k Ct[n,k] D2[b,k,(m,i)].  Same; RMW epilogue.
// ---------------------------------------------------------------------------
__global__ void __launch_bounds__(128) k3b_up(float* __restrict__ out) {
    int t = threadIdx.x, lane = t & 31, w = t >> 5;
    int ct = blockIdx.x, rs = blockIdx.y, b = blockIdx.z;
    int gr = lane >> 2, tg = lane & 3;
    int colbase = ct * 256 + w * 64;

    const float* B = d_D2 + (size_t)b * 32 * NI;
    const uint4* Af = (const uint4*)d_Afrag;

    uint32_t bf[4][8][2];
#pragma unroll
    for (int kf = 0; kf < 4; kf++) {
        int r0 = kf * 8 + tg;
#pragma unroll
        for (int cf = 0; cf < 8; cf++) {
            int col = colbase + cf * 8 + gr;
            bf[kf][cf][0] = __float_as_uint(__ldg(&B[(size_t)r0 * NI + col]));
            bf[kf][cf][1] = __float_as_uint(__ldg(&B[(size_t)(r0 + 4) * NI + col]));
        }
    }

#pragma unroll
    for (int rr = 0; rr < 4; rr++) {
        int rf = rs * 4 + rr;
        int r0 = rf * 16;

        U4F a[4];
#pragma unroll
        for (int kf = 0; kf < 4; kf++)
            a[kf].u4 = __ldg(&Af[(rf * 4 + kf) * 32 + lane]);

        float acc[8][4];
#pragma unroll
        for (int cf = 0; cf < 8; cf++)
#pragma unroll
            for (int q = 0; q < 4; q++) acc[cf][q] = 0.f;

#pragma unroll
        for (int cf = 0; cf < 8; cf++)
#pragma unroll
            for (int kf = 0; kf < 4; kf++)
                mma_tf32(acc[cf], a[kf].u, bf[kf][cf][0], bf[kf][cf][1]);

        // rows = n, cols = (m,i): out[b][m][n][i]
#pragma unroll
        for (int cf = 0; cf < 8; cf++) {
            int cb = colbase + cf * 8;        // 8-aligned, one m per cf
            int m  = cb >> 5;
            int ib = (cb & 31) + 2 * tg;
            int n  = r0 + gr;
            size_t ad = ((size_t)b * 256 + m) * NI + n * 32 + ib;
            float2 o0 = *(float2*)&out[ad];
            o0.x += acc[cf][0];
            o0.y += acc[cf][1];
            *(float2*)&out[ad] = o0;
            size_t ad2 = ad + 8 * 32;         // row n+8
            float2 o1 = *(float2*)&out[ad2];
            o1.x += acc[cf][2];
            o1.y += acc[cf][3];
            *(float2*)&out[ad2] = o1;
        }
    }
}

// ---------------------------------------------------------------------------
extern "C" void kernel_launch(void* const* d_in, const int* in_sizes, int n_in,
                              void* d_out, int out_size) {
    const float* x = (const float*)d_in[0];
    float* out = (float*)d_out;

    init_C_kernel<<<32, 256>>>();
    init_A_kernel<<<8, 256>>>();
    k1_down_m<<<dim3(64, 8), 128>>>(x);
    k2_down_n<<<dim3(64, 8), 128>>>(x);
    k3a_up<<<dim3(32, 4, 8), 128>>>(out);
    k3b_up<<<dim3(32, 4, 8), 128>>>(out);
}